// round 11
// baseline (speedup 1.0000x reference)
#include <cuda_runtime.h>

// DegreePrediction: y[u] = sum_{s,t,v} (x*W_t)[s,t] * (W_r*r_zeros + r_const)[s,t,u,v]
// N = 80. Three 80^4 fp32 tensors (491.5 MB) streamed once.
//
// R11: persistent blocks (GRID=592, one wave) + dynamic work stealing at
// 1-slice granularity. R7 (short blocks) beat static-persistent R9/R10 by
// 2.5us purely through scheduler rebalancing; stealing gives the same balance
// without R7's 1600 epilogues or wave transitions. Pop is issued at slice
// start and joined 4 pipelined iterations later -> latency hidden. Parity
// double-buffer on the shared broadcast avoids cross-iteration races.
//
// Layout: slice = 1600 contiguous float4 = 5*320; iter j reads float4
// tid + 320*j of the slice -> u = tid/20 + 16*j (constant per thread,j).

#define NN 80
#define SLICE_F4 1600
#define THREADS 320
#define J_ITERS 5
#define TOTAL_SLICES (NN * NN)      // 6400
#define GRID 592                    // 148 SMs * 4 blocks, single wave

__device__ float    g_scratch[NN];   // zero at load; kernel restores to zero
__device__ unsigned g_count;         // ditto
__device__ unsigned g_next;          // ditto

__device__ __forceinline__ unsigned atom_inc_acq_rel(unsigned* p) {
    unsigned old;
    asm volatile("atom.add.acq_rel.gpu.global.u32 %0, [%1], 1;"
                 : "=r"(old) : "l"(p) : "memory");
    return old;
}

__global__ __launch_bounds__(THREADS, 4)
void degree_pred_kernel(const float* __restrict__ x,
                        const float* __restrict__ r_zeros,
                        const float* __restrict__ r_const,
                        const float* __restrict__ weights_t,
                        const float* __restrict__ weights_r,
                        float* __restrict__ out)
{
    __shared__ float y_part[J_ITERS][THREADS];
    __shared__ unsigned sh_next[2];   // parity double-buffer for pop broadcast
    __shared__ bool is_last;
    const int tid = threadIdx.x;

    const float4* __restrict__ Z = reinterpret_cast<const float4*>(r_zeros);
    const float4* __restrict__ C = reinterpret_cast<const float4*>(r_const);
    const float4* __restrict__ W = reinterpret_cast<const float4*>(weights_r);

    float acc[J_ITERS];
#pragma unroll
    for (int j = 0; j < J_ITERS; j++) acc[j] = 0.0f;

    // first slice = bid (implicit); steals hand out GRID..TOTAL_SLICES-1
    int s = blockIdx.x;
    {
        const size_t b = (size_t)s * SLICE_F4 + tid;
        // pointers advance by +320 float4 per iteration (pure IADD chain)
        // initialized below via Z+b etc.
    }
    const float4* pz = Z + ((size_t)s * SLICE_F4 + tid);
    const float4* pc = C + ((size_t)s * SLICE_F4 + tid);
    const float4* pw = W + ((size_t)s * SLICE_F4 + tid);
    float a_cur = __ldg(&x[s]) * __ldg(&weights_t[s]);

    float4 z0 = __ldcs(pz);
    float4 c0 = __ldcs(pc);
    float4 w0 = __ldcs(pw);

    int par = 0;
    for (;;) {
        // issue the steal for the NEXT slice now; join after 4 iterations
        if (tid == 0) sh_next[par] = GRID + atomicAdd(&g_next, 1u);

        // j = 0..3: prefetch next iteration within this slice
#pragma unroll
        for (int j = 0; j < J_ITERS - 1; j++) {
            pz += THREADS; pc += THREADS; pw += THREADS;
            const float4 z1 = __ldcs(pz);
            const float4 c1 = __ldcs(pc);
            const float4 w1 = __ldcs(pw);
            float t = (c0.x + c0.y) + (c0.z + c0.w);
            t = fmaf(w0.x, z0.x, t);
            t = fmaf(w0.y, z0.y, t);
            t = fmaf(w0.z, z0.z, t);
            t = fmaf(w0.w, z0.w, t);
            acc[j] = fmaf(a_cur, t, acc[j]);
            z0 = z1; c0 = c1; w0 = w1;
        }

        __syncthreads();                       // join the steal
        const unsigned sn = sh_next[par];
        par ^= 1;
        const bool has_next = (sn < (unsigned)TOTAL_SLICES);
        const unsigned sc = has_next ? sn : (unsigned)s;   // clamped, no OOB
        const size_t nb = (size_t)sc * SLICE_F4 + tid;
        const float a_next = __ldg(&x[sc]) * __ldg(&weights_t[sc]);

        // j = 4: prefetch iteration 0 of the next slice
        {
            float4 z1, c1, w1;
            if (has_next) {
                z1 = __ldcs(Z + nb);
                c1 = __ldcs(C + nb);
                w1 = __ldcs(W + nb);
            }
            float t = (c0.x + c0.y) + (c0.z + c0.w);
            t = fmaf(w0.x, z0.x, t);
            t = fmaf(w0.y, z0.y, t);
            t = fmaf(w0.z, z0.z, t);
            t = fmaf(w0.w, z0.w, t);
            acc[J_ITERS - 1] = fmaf(a_cur, t, acc[J_ITERS - 1]);
            z0 = z1; c0 = c1; w0 = w1;
        }

        if (!has_next) break;
        s = (int)sn;
        pz = Z + nb; pc = C + nb; pw = W + nb;
        a_cur = a_next;
    }

    // ---- epilogue (once per block): STS transpose + 80-thread gather ----
#pragma unroll
    for (int j = 0; j < J_ITERS; j++)
        y_part[j][tid] = acc[j];
    __syncthreads();

    if (tid < NN) {
        const int u = tid;
        const int j = u >> 4;            // u / 16
        const int b = (u & 15) * 20;     // first of 20 contributing threads
        float sum = 0.0f;
#pragma unroll
        for (int d = 0; d < 20; d++)
            sum += y_part[j][b + d];
        atomicAdd(&g_scratch[u], sum);   // relaxed; published by acq_rel below
    }
    __syncthreads();

    // ---- last-block finalize ----
    if (tid == 0)
        is_last = (atom_inc_acq_rel(&g_count) == (unsigned)(GRID - 1));
    __syncthreads();

    if (is_last) {
        if (tid < NN) {
            float v = __ldcg(&g_scratch[tid]);   // L2 read, coherent w/ atomics
            out[tid] = v;
            g_scratch[tid] = 0.0f;               // restore initial state
        }
        __syncthreads();
        if (tid == 0) { g_count = 0u; g_next = 0u; }   // restore initial state
    }
}

extern "C" void kernel_launch(void* const* d_in, const int* in_sizes, int n_in,
                              void* d_out, int out_size)
{
    const float* x         = (const float*)d_in[0];
    const float* r_zeros   = (const float*)d_in[1];
    const float* r_const   = (const float*)d_in[2];
    const float* weights_t = (const float*)d_in[3];
    const float* weights_r = (const float*)d_in[4];
    float* out = (float*)d_out;

    degree_pred_kernel<<<GRID, THREADS>>>(x, r_zeros, r_const,
                                          weights_t, weights_r, out);
}